// round 13
// baseline (speedup 1.0000x reference)
#include <cuda_runtime.h>
#include <cuda_bf16.h>
#include <math.h>
#include <stdint.h>

#define BB 4
#define CC 64
#define HH 96
#define WW 320
#define HP 97   // conv rows 0..96 (row 96 = top kernel row on x[95])

// Scratch (static device globals: allowed; no runtime allocation)
__device__ float g_conv[BB*CC*HP*WW];   // ~31.8 MB
__device__ float g_mid [BB*CC*HH*WW];   // ~31.5 MB
__device__ float g_T   [BB*CC*16*WW];   // ~5.2 MB  (top-row conv at 16 special rows)

// rows f_d-1, f_d for f = {1,12,22,33,44,54,65,76}
__constant__ int c_R16[16] = {0,1, 11,12, 21,22, 32,33, 43,44, 53,54, 64,65, 75,76};

// ---------------------------------------------------------------------------
// bf16 mma.sync m16n8k16 (row.col), fp32 accumulate
// ---------------------------------------------------------------------------
#define MMA_BF16(d, a0, a1, a2, a3, b0, b1)                                  \
    asm volatile(                                                            \
        "mma.sync.aligned.m16n8k16.row.col.f32.bf16.bf16.f32 "               \
        "{%0,%1,%2,%3}, {%4,%5,%6,%7}, {%8,%9}, {%0,%1,%2,%3};"              \
        : "+f"(d[0]), "+f"(d[1]), "+f"(d[2]), "+f"(d[3])                     \
        : "r"(a0), "r"(a1), "r"(a2), "r"(a3), "r"(b0), "r"(b1))

// ---------------------------------------------------------------------------
// conv3 as implicit GEMM on tensor cores, bf16 2-way split (3 passes).
// D[co=64, n=64 cols] for one (b, y). K = ci*9 = 576, chunked 8ci (K_sub=72,
// padded to 80). grid = (WW/64=5, HP=97, BB).  256 threads = 8 warps:
// warp = (co group of 16) x (n half of 32). Output rows 0..96 into g_conv.
// ---------------------------------------------------------------------------
__global__ __launch_bounds__(256, 2)
void conv3_mma_kernel(const float* __restrict__ in_ext, const float* __restrict__ wk)
{
    const float* in = in_ext ? in_ext : g_mid;

    // SMEM plan (47488 B total):
    //   Xr    [8 ci][3 rows][68] f32       @ 0      (6528 B)
    //   As_hi [64 co][80 k]  bf16          @ 6528   (10240 B)
    //   As_lo                              @ 16768
    //   Bs_hi [64 n ][80 k]  bf16          @ 27008
    //   Bs_lo                              @ 37248  (end 47488)
    __shared__ __align__(16) unsigned char sm[47488];
    float*          Xr    = (float*)sm;
    __nv_bfloat16*  As_hi = (__nv_bfloat16*)(sm + 6528);
    __nv_bfloat16*  As_lo = (__nv_bfloat16*)(sm + 16768);
    __nv_bfloat16*  Bs_hi = (__nv_bfloat16*)(sm + 27008);
    __nv_bfloat16*  Bs_lo = (__nv_bfloat16*)(sm + 37248);
    const uint32_t* Ah32  = (const uint32_t*)As_hi;
    const uint32_t* Al32  = (const uint32_t*)As_lo;
    const uint32_t* Bh32  = (const uint32_t*)Bs_hi;
    const uint32_t* Bl32  = (const uint32_t*)Bs_lo;

    const int x0   = blockIdx.x * 64;
    const int y    = blockIdx.y;            // 0..96
    const int b    = blockIdx.z;
    const int tid  = threadIdx.x;
    const int w    = tid >> 5;
    const int lane = tid & 31;
    const int gq   = lane >> 2;             // group id 0..7
    const int c4   = lane & 3;              // thread-in-group 0..3
    const int cobase = (w >> 1) * 16;
    const int nbase  = (w & 1) * 32;

    // zero all smem once (provides k=72..79 zero padding permanently)
    for (int i = tid; i < 47488/4; i += 256) ((uint32_t*)sm)[i] = 0u;

    float acc[4][4];
    #pragma unroll
    for (int nf = 0; nf < 4; nf++)
        #pragma unroll
        for (int e = 0; e < 4; e++) acc[nf][e] = 0.f;

    __syncthreads();

    #pragma unroll 1
    for (int ci0 = 0; ci0 < CC; ci0 += 8) {
        // ---- phase 1: raw input strip + weight split ----
        for (int idx = tid; idx < 1584; idx += 256) {          // 8*3*66
            int ci_l = idx / 198;  int rem = idx - ci_l * 198;
            int r    = rem / 66;   int c   = rem - r * 66;
            int gy = y + r - 1, gx = x0 - 1 + c;
            float v = 0.f;
            if ((unsigned)gy < (unsigned)HH && (unsigned)gx < (unsigned)WW)
                v = in[((size_t)(b*CC + ci0 + ci_l) * HH + gy) * WW + gx];
            Xr[ci_l*204 + r*68 + c] = v;
        }
        for (int idx = tid; idx < 4608; idx += 256) {          // 64co * 72k
            int co = idx / 72;  int k = idx - co * 72;
            float v = wk[(size_t)co * 576 + (size_t)ci0 * 9 + k];
            __nv_bfloat16 h = __float2bfloat16(v);
            __nv_bfloat16 l = __float2bfloat16(v - __bfloat162float(h));
            As_hi[co*80 + k] = h;
            As_lo[co*80 + k] = l;
        }
        __syncthreads();

        // ---- phase 2: im2col expand + input split ----
        for (int idx = tid; idx < 4608; idx += 256) {          // 64n * 72k
            int n = idx / 72;  int k = idx - n * 72;
            int ci_l = k / 9;  int t = k - ci_l * 9;
            int ky = t / 3;    int kx = t - ky * 3;
            float v = Xr[ci_l*204 + ky*68 + n + kx];
            __nv_bfloat16 h = __float2bfloat16(v);
            __nv_bfloat16 l = __float2bfloat16(v - __bfloat162float(h));
            Bs_hi[n*80 + k] = h;
            Bs_lo[n*80 + k] = l;
        }
        __syncthreads();

        // ---- phase 3: MMA, K_sub = 80 = 5 x k16, 3 split passes ----
        #pragma unroll
        for (int kt = 0; kt < 5; kt++) {
            const int kw = kt*8 + c4;                    // word offset in row
            const int ra = (cobase + gq) * 40 + kw;
            const int rb = ra + 8*40;
            uint32_t ah0 = Ah32[ra],   ah1 = Ah32[rb];
            uint32_t ah2 = Ah32[ra+4], ah3 = Ah32[rb+4];
            uint32_t al0 = Al32[ra],   al1 = Al32[rb];
            uint32_t al2 = Al32[ra+4], al3 = Al32[rb+4];
            #pragma unroll
            for (int nf = 0; nf < 4; nf++) {
                const int rn = (nbase + nf*8 + gq) * 40 + kw;
                uint32_t bh0 = Bh32[rn], bh1 = Bh32[rn+4];
                uint32_t bl0 = Bl32[rn], bl1 = Bl32[rn+4];
                MMA_BF16(acc[nf], ah0, ah1, ah2, ah3, bh0, bh1);   // hi*hi
                MMA_BF16(acc[nf], ah0, ah1, ah2, ah3, bl0, bl1);   // hi*lo
                MMA_BF16(acc[nf], al0, al1, al2, al3, bh0, bh1);   // lo*hi
            }
        }
        __syncthreads();
    }

    // ---- epilogue: D[g][2c..2c+1] / D[g+8][...] per fragment ----
    #pragma unroll
    for (int nf = 0; nf < 4; nf++) {
        int co0 = cobase + gq;
        int n0  = x0 + nbase + nf*8 + c4*2;
        float2 p01 = make_float2(acc[nf][0], acc[nf][1]);
        float2 p23 = make_float2(acc[nf][2], acc[nf][3]);
        *(float2*)&g_conv[((size_t)(b*CC + co0    ) * HP + y) * WW + n0] = p01;
        *(float2*)&g_conv[((size_t)(b*CC + co0 + 8) * HP + y) * WW + n0] = p23;
    }
}

// ---------------------------------------------------------------------------
// Top-kernel-row conv T[r] = sum_{ci,kx} W[co,ci,0,kx] * x[ci, r, x+kx-1]
// at the 16 rows in c_R16. grid = (10, 4 row-groups, BB), 256 threads.
// (fp32 scalar — tiny kernel, exactness of correction preserved)
// ---------------------------------------------------------------------------
__global__ __launch_bounds__(256)
void trow_kernel(const float* __restrict__ in_ext, const float* __restrict__ wk)
{
    const float* in = in_ext ? in_ext : g_mid;
    __shared__ __align__(16) float Xs4[4][34];
    __shared__ __align__(16) float Ws3[3][64];

    const int x0  = blockIdx.x * 32;
    const int rg  = blockIdx.y;         // 0..3 -> rows c_R16[4*rg .. 4*rg+3]
    const int b   = blockIdx.z;
    const int tid = threadIdx.x;
    const int cog = tid >> 5;           // 0..7
    const int lx  = tid & 31;

    float acc[8][4];
    #pragma unroll
    for (int i = 0; i < 8; i++)
        #pragma unroll
        for (int r = 0; r < 4; r++) acc[i][r] = 0.f;

    for (int ci = 0; ci < CC; ci++) {
        for (int idx = tid; idx < 136; idx += 256) {
            int r = idx / 34, c = idx - r * 34;
            int gy = c_R16[rg*4 + r];           // always in [0,96)
            int gx = x0 - 1 + c;
            float v = 0.f;
            if (gx >= 0 && gx < WW) v = in[((size_t)(b*CC + ci) * HH + gy) * WW + gx];
            Xs4[r][c] = v;
        }
        for (int idx = tid; idx < 192; idx += 256) {
            int co = idx / 3, kx = idx - co * 3;
            Ws3[kx][co] = wk[(co*CC + ci)*9 + kx];   // ky = 0 row
        }
        __syncthreads();

        #pragma unroll
        for (int rr = 0; rr < 4; rr++) {
            float xv[3] = { Xs4[rr][lx], Xs4[rr][lx + 1], Xs4[rr][lx + 2] };
            #pragma unroll
            for (int kx = 0; kx < 3; kx++) {
                const float4* wp = reinterpret_cast<const float4*>(&Ws3[kx][0]) + cog*2;
                float4 wa = wp[0], wb = wp[1];
                float wv[8] = {wa.x, wa.y, wa.z, wa.w, wb.x, wb.y, wb.z, wb.w};
                #pragma unroll
                for (int i = 0; i < 8; i++)
                    acc[i][rr] = fmaf(wv[i], xv[kx], acc[i][rr]);
            }
        }
        __syncthreads();
    }

    #pragma unroll
    for (int i = 0; i < 8; i++) {
        int co = cog*8 + i;
        #pragma unroll
        for (int rr = 0; rr < 4; rr++)
            g_T[((size_t)(b*CC + co) * 16 + rg*4 + rr) * WW + x0 + lx] = acc[i][rr];
    }
}

// ---------------------------------------------------------------------------
// Plane-blend + max + bias + relu.
// out[y] = relu(bias + max_d [(1-w_d)*Cz[y+f_d] + w_d*Cz[y+f_d+1]])  (rows>96 -> 0)
// y==0 subtracts the top-pad correction using g_T.
// grid = (WW/32=10, BB*CC), 256 threads. Shared: full 97-row column strip.
// ---------------------------------------------------------------------------
__global__ __launch_bounds__(256)
void blend_kernel(const float* __restrict__ bias, float* __restrict__ out_ext)
{
    float* out = out_ext ? out_ext : g_mid;
    __shared__ float s[HP][32];

    const int x0  = blockIdx.x * 32;
    const int bc  = blockIdx.y;                 // b*CC + c
    const int tid = threadIdx.x;
    const float* src = g_conv + (size_t)bc * HP * WW + x0;

    for (int idx = tid; idx < HP*32; idx += 256) {
        int r = idx >> 5, c = idx & 31;
        s[r][c] = src[(size_t)r * WW + c];
    }
    __syncthreads();

    const int fi[8]   = {1, 12, 22, 33, 44, 54, 65, 76};
    const float wf[8] = {0.52f, 0.16f, 0.80f, 0.44f, 0.08f, 0.72f, 0.36f, 0.0f};

    const int lx = tid & 31;
    const int ty = tid >> 5;                    // 0..7, each handles 12 rows
    const float bv = bias[bc & (CC - 1)];

    for (int yy = 0; yy < 12; yy++) {
        int y = ty * 12 + yy;
        float m = -3.0e38f;
        #pragma unroll
        for (int d = 0; d < 8; d++) {
            int r0 = y + fi[d];
            float v0 = (r0 <= HH) ? s[r0][lx]     : 0.f;   // row <= 96
            float v1 = (r0 <  HH) ? s[r0 + 1][lx] : 0.f;   // row+1 <= 96
            float v  = (1.f - wf[d]) * v0 + wf[d] * v1;
            m = fmaxf(m, v);
        }
        if (y == 0) {
            // exact top-boundary correction: subtract K_top applied to warpedz[-1]
            m = -3.0e38f;
            #pragma unroll
            for (int d = 0; d < 8; d++) {
                float T0 = g_T[((size_t)bc * 16 + 2*d    ) * WW + x0 + lx];
                float T1 = g_T[((size_t)bc * 16 + 2*d + 1) * WW + x0 + lx];
                float v0 = s[fi[d]][lx]     - T0;
                float v1 = s[fi[d] + 1][lx] - T1;
                float v  = (1.f - wf[d]) * v0 + wf[d] * v1;
                m = fmaxf(m, v);
            }
        }
        out[((size_t)bc * HH + y) * WW + x0 + lx] = fmaxf(m + bv, 0.f);
    }
}

// ---------------------------------------------------------------------------
extern "C" void kernel_launch(void* const* d_in, const int* in_sizes, int n_in,
                              void* d_out, int out_size)
{
    const float* x  = (const float*)d_in[0];
    const float* W1 = (const float*)d_in[1];
    const float* b1 = (const float*)d_in[2];
    const float* W2 = (const float*)d_in[3];
    const float* b2 = (const float*)d_in[4];
    float* out = (float*)d_out;

    dim3 gm(WW/64, HP, BB);             // 5 x 97 x 4
    dim3 gt(WW/32, 4, BB);              // 10 x 4 x 4
    dim3 gb(WW/32, BB*CC);              // 10 x 256

    // Layer 1
    conv3_mma_kernel<<<gm, 256>>>(x, W1);
    trow_kernel     <<<gt, 256>>>(x, W1);
    blend_kernel    <<<gb, 256>>>(b1, nullptr);   // -> g_mid (includes relu)
    // Layer 2
    conv3_mma_kernel<<<gm, 256>>>(nullptr, W2);   // in = g_mid
    trow_kernel     <<<gt, 256>>>(nullptr, W2);
    blend_kernel    <<<gb, 256>>>(b2, out);
}

// round 15
// speedup vs baseline: 1.4757x; 1.4757x over previous
#include <cuda_runtime.h>
#include <cuda_bf16.h>
#include <math.h>
#include <stdint.h>

#define BB 4
#define CC 64
#define HH 96
#define WW 320
#define HP 97   // conv rows 0..96 (row 96 = top kernel row on x[95])

// Scratch (static device globals: allowed; no runtime allocation)
__device__ float g_conv[BB*CC*HP*WW];   // ~31.8 MB
__device__ float g_mid [BB*CC*HH*WW];   // ~31.5 MB
__device__ float g_T   [BB*CC*16*WW];   // ~5.2 MB

// Pre-split weights, fragment-ready: [co][tap][chunk][perm(ci16)] bf16
__device__ __align__(16) __nv_bfloat16 g_Wh[64*9*4*16];   // 73728 B
__device__ __align__(16) __nv_bfloat16 g_Wl[64*9*4*16];

// rows f_d-1, f_d for f = {1,12,22,33,44,54,65,76}
__constant__ int c_R16[16] = {0,1, 11,12, 21,22, 32,33, 43,44, 53,54, 64,65, 75,76};

#define MMA_BF16(d, a0, a1, a2, a3, b0, b1)                                  \
    asm volatile(                                                            \
        "mma.sync.aligned.m16n8k16.row.col.f32.bf16.bf16.f32 "               \
        "{%0,%1,%2,%3}, {%4,%5,%6,%7}, {%8,%9}, {%0,%1,%2,%3};"              \
        : "+f"(d[0]), "+f"(d[1]), "+f"(d[2]), "+f"(d[3])                     \
        : "r"(a0), "r"(a1), "r"(a2), "r"(a3), "r"(b0), "r"(b1))

// pair-interleave permutation: word w0=k{0,1}, w1=k{8,9}, w2=k{2,3}, w3=k{10,11}, ...
__host__ __device__ __forceinline__ int perm16(int ci) {
    return ((ci & 6) << 1) | ((ci >> 3) << 1) | (ci & 1);
}

// ---------------------------------------------------------------------------
// Weight split precompute: RN hi/lo bf16, permuted fragment layout. Runs once
// per layer (36864 elements).
// ---------------------------------------------------------------------------
__global__ void wsplit_kernel(const float* __restrict__ wk)
{
    int idx = blockIdx.x * 256 + threadIdx.x;
    if (idx >= 64*9*64) return;
    int co  = idx / 576;
    int rem = idx - co * 576;
    int tap = rem / 64;
    int ci  = rem - tap * 64;
    float v = wk[((size_t)co * 64 + ci) * 9 + tap];
    __nv_bfloat16 h = __float2bfloat16(v);
    __nv_bfloat16 l = __float2bfloat16(v - __bfloat162float(h));
    int dst = ((co*9 + tap)*4 + (ci >> 4))*16 + perm16(ci & 15);
    g_Wh[dst] = h;
    g_Wl[dst] = l;
}

// ---------------------------------------------------------------------------
// conv3 as 9 shifted K=64 GEMMs on tensor cores (no im2col materialization).
// Block: 2 output rows x 64 cols x 64 co. 8 warps = 4 co-groups x 2 n-halves.
// ci chunked by 16 (one k16 MMA step per tap). bf16 2-way split, 3 passes.
// grid = (WW/64=5, ceil(HP/2)=49, BB). Output rows 0..96 into g_conv.
// ---------------------------------------------------------------------------
__global__ __launch_bounds__(256, 2)
void conv3_mma_kernel(const float* __restrict__ in_ext)
{
    const float* in = in_ext ? in_ext : g_mid;

    // X strip: [4 rows][68 cols][stride 10 words: 8 real (16 permuted ci) + 2 pad]
    __shared__ __align__(16) uint16_t Xh[4*68*20];   // 10880 B
    __shared__ __align__(16) uint16_t Xl[4*68*20];   // 10880 B

    const int x0   = blockIdx.x * 64;
    const int y0   = blockIdx.y * 2;
    const int b    = blockIdx.z;
    const int tid  = threadIdx.x;
    const int w    = tid >> 5;
    const int lane = tid & 31;
    const int gq   = lane >> 2;             // 0..7
    const int c4   = lane & 3;              // 0..3
    const int cobase = (w >> 1) * 16;
    const int nb     = (w & 1) * 32;
    const int co_a   = cobase + gq;
    const int co_b   = co_a + 8;

    const uint2* WhA = (const uint2*)g_Wh;  // u64 granules: {a0,a2} / {a1,a3}
    const uint2* WlA = (const uint2*)g_Wl;

    float acc[8][4];
    #pragma unroll
    for (int i = 0; i < 8; i++)
        #pragma unroll
        for (int e = 0; e < 4; e++) acc[i][e] = 0.f;

    #pragma unroll 1
    for (int cw = 0; cw < 4; cw++) {        // ci chunk of 16
        const int ci0 = cw * 16;
        // ---- stage raw strip: 16ci x 4rows x 66cols, truncation split ----
        #pragma unroll 1
        for (int idx = tid; idx < 4224; idx += 256) {
            int ci_l = idx / 264;
            int rem  = idx - ci_l * 264;
            int r    = rem / 66;
            int c    = rem - r * 66;
            int gy = y0 - 1 + r, gx = x0 - 1 + c;
            float v = 0.f;
            if ((unsigned)gy < (unsigned)HH && (unsigned)gx < (unsigned)WW)
                v = in[((size_t)(b*CC + ci0 + ci_l) * HH + gy) * WW + gx];
            unsigned u = __float_as_uint(v);
            float hf = __uint_as_float(u & 0xFFFF0000u);
            __nv_bfloat16 l = __float2bfloat16(v - hf);
            int h_idx = (r*68 + c)*20 + perm16(ci_l);
            Xh[h_idx] = (uint16_t)(u >> 16);
            Xl[h_idx] = *(const uint16_t*)&l;
        }
        __syncthreads();

        // ---- 9 shifted tap-GEMMs, K=16 each, 3 split passes ----
        #pragma unroll
        for (int ky = 0; ky < 3; ky++) {
            #pragma unroll
            for (int kx = 0; kx < 3; kx++) {
                const int tap = ky*3 + kx;
                uint2 ha = WhA[ ((co_a*9 + tap)*4 + cw)*4 + c4 ];  // {a0,a2} hi
                uint2 hb = WhA[ ((co_b*9 + tap)*4 + cw)*4 + c4 ];  // {a1,a3} hi
                uint2 la = WlA[ ((co_a*9 + tap)*4 + cw)*4 + c4 ];
                uint2 lb = WlA[ ((co_b*9 + tap)*4 + cw)*4 + c4 ];
                #pragma unroll
                for (int ro = 0; ro < 2; ro++) {
                    const int rbase = (ro + ky)*68;
                    #pragma unroll
                    for (int cf = 0; cf < 4; cf++) {
                        const int col  = nb + cf*8 + gq + kx;
                        const int word = (rbase + col)*10 + 2*c4;
                        uint2 bh = *(const uint2*)((const char*)Xh + (size_t)word*4);
                        uint2 bl = *(const uint2*)((const char*)Xl + (size_t)word*4);
                        float* d = acc[ro*4 + cf];
                        MMA_BF16(d, ha.x, hb.x, ha.y, hb.y, bh.x, bh.y);  // hi*hi
                        MMA_BF16(d, ha.x, hb.x, ha.y, hb.y, bl.x, bl.y);  // hi*lo
                        MMA_BF16(d, la.x, lb.x, la.y, lb.y, bh.x, bh.y);  // lo*hi
                    }
                }
            }
        }
        __syncthreads();
    }

    // ---- epilogue ----
    #pragma unroll
    for (int ro = 0; ro < 2; ro++) {
        const int y = y0 + ro;
        if (y >= HP) continue;
        #pragma unroll
        for (int cf = 0; cf < 4; cf++) {
            const float* d = acc[ro*4 + cf];
            const int n0 = x0 + nb + cf*8 + 2*c4;
            *(float2*)&g_conv[((size_t)(b*CC + co_a) * HP + y) * WW + n0] =
                make_float2(d[0], d[1]);
            *(float2*)&g_conv[((size_t)(b*CC + co_b) * HP + y) * WW + n0] =
                make_float2(d[2], d[3]);
        }
    }
}

// ---------------------------------------------------------------------------
// Top-kernel-row conv T[r] at the 16 rows in c_R16 (fp32 exact correction).
// grid = (10, 4, BB), 256 threads.
// ---------------------------------------------------------------------------
__global__ __launch_bounds__(256)
void trow_kernel(const float* __restrict__ in_ext, const float* __restrict__ wk)
{
    const float* in = in_ext ? in_ext : g_mid;
    __shared__ __align__(16) float Xs4[4][34];
    __shared__ __align__(16) float Ws3[3][64];

    const int x0  = blockIdx.x * 32;
    const int rg  = blockIdx.y;
    const int b   = blockIdx.z;
    const int tid = threadIdx.x;
    const int cog = tid >> 5;
    const int lx  = tid & 31;

    float acc[8][4];
    #pragma unroll
    for (int i = 0; i < 8; i++)
        #pragma unroll
        for (int r = 0; r < 4; r++) acc[i][r] = 0.f;

    for (int ci = 0; ci < CC; ci++) {
        for (int idx = tid; idx < 136; idx += 256) {
            int r = idx / 34, c = idx - r * 34;
            int gy = c_R16[rg*4 + r];
            int gx = x0 - 1 + c;
            float v = 0.f;
            if (gx >= 0 && gx < WW) v = in[((size_t)(b*CC + ci) * HH + gy) * WW + gx];
            Xs4[r][c] = v;
        }
        for (int idx = tid; idx < 192; idx += 256) {
            int co = idx / 3, kx = idx - co * 3;
            Ws3[kx][co] = wk[(co*CC + ci)*9 + kx];
        }
        __syncthreads();

        #pragma unroll
        for (int rr = 0; rr < 4; rr++) {
            float xv[3] = { Xs4[rr][lx], Xs4[rr][lx + 1], Xs4[rr][lx + 2] };
            #pragma unroll
            for (int kx = 0; kx < 3; kx++) {
                const float4* wp = reinterpret_cast<const float4*>(&Ws3[kx][0]) + cog*2;
                float4 wa = wp[0], wb = wp[1];
                float wv[8] = {wa.x, wa.y, wa.z, wa.w, wb.x, wb.y, wb.z, wb.w};
                #pragma unroll
                for (int i = 0; i < 8; i++)
                    acc[i][rr] = fmaf(wv[i], xv[kx], acc[i][rr]);
            }
        }
        __syncthreads();
    }

    #pragma unroll
    for (int i = 0; i < 8; i++) {
        int co = cog*8 + i;
        #pragma unroll
        for (int rr = 0; rr < 4; rr++)
            g_T[((size_t)(b*CC + co) * 16 + rg*4 + rr) * WW + x0 + lx] = acc[i][rr];
    }
}

// ---------------------------------------------------------------------------
// Plane-blend + max + bias + relu (y==0 uses exact top-pad correction).
// grid = (10, BB*CC), 256 threads.
// ---------------------------------------------------------------------------
__global__ __launch_bounds__(256)
void blend_kernel(const float* __restrict__ bias, float* __restrict__ out_ext)
{
    float* out = out_ext ? out_ext : g_mid;
    __shared__ float s[HP][32];

    const int x0  = blockIdx.x * 32;
    const int bc  = blockIdx.y;
    const int tid = threadIdx.x;
    const float* src = g_conv + (size_t)bc * HP * WW + x0;

    for (int idx = tid; idx < HP*32; idx += 256) {
        int r = idx >> 5, c = idx & 31;
        s[r][c] = src[(size_t)r * WW + c];
    }
    __syncthreads();

    const int fi[8]   = {1, 12, 22, 33, 44, 54, 65, 76};
    const float wf[8] = {0.52f, 0.16f, 0.80f, 0.44f, 0.08f, 0.72f, 0.36f, 0.0f};

    const int lx = tid & 31;
    const int ty = tid >> 5;
    const float bv = bias[bc & (CC - 1)];

    for (int yy = 0; yy < 12; yy++) {
        int y = ty * 12 + yy;
        float m = -3.0e38f;
        #pragma unroll
        for (int d = 0; d < 8; d++) {
            int r0 = y + fi[d];
            float v0 = (r0 <= HH) ? s[r0][lx]     : 0.f;
            float v1 = (r0 <  HH) ? s[r0 + 1][lx] : 0.f;
            float v  = (1.f - wf[d]) * v0 + wf[d] * v1;
            m = fmaxf(m, v);
        }
        if (y == 0) {
            m = -3.0e38f;
            #pragma unroll
            for (int d = 0; d < 8; d++) {
                float T0 = g_T[((size_t)bc * 16 + 2*d    ) * WW + x0 + lx];
                float T1 = g_T[((size_t)bc * 16 + 2*d + 1) * WW + x0 + lx];
                float v0 = s[fi[d]][lx]     - T0;
                float v1 = s[fi[d] + 1][lx] - T1;
                float v  = (1.f - wf[d]) * v0 + wf[d] * v1;
                m = fmaxf(m, v);
            }
        }
        out[((size_t)bc * HH + y) * WW + x0 + lx] = fmaxf(m + bv, 0.f);
    }
}

// ---------------------------------------------------------------------------
extern "C" void kernel_launch(void* const* d_in, const int* in_sizes, int n_in,
                              void* d_out, int out_size)
{
    const float* x  = (const float*)d_in[0];
    const float* W1 = (const float*)d_in[1];
    const float* b1 = (const float*)d_in[2];
    const float* W2 = (const float*)d_in[3];
    const float* b2 = (const float*)d_in[4];
    float* out = (float*)d_out;

    dim3 gm(WW/64, (HP + 1) / 2, BB);   // 5 x 49 x 4
    dim3 gt(WW/32, 4, BB);              // 10 x 4 x 4
    dim3 gb(WW/32, BB*CC);              // 10 x 256

    // Layer 1
    wsplit_kernel   <<<144, 256>>>(W1);
    conv3_mma_kernel<<<gm, 256>>>(x);
    trow_kernel     <<<gt, 256>>>(x, W1);
    blend_kernel    <<<gb, 256>>>(b1, nullptr);   // -> g_mid (includes relu)
    // Layer 2
    wsplit_kernel   <<<144, 256>>>(W2);
    conv3_mma_kernel<<<gm, 256>>>(nullptr);       // in = g_mid
    trow_kernel     <<<gt, 256>>>(nullptr, W2);
    blend_kernel    <<<gb, 256>>>(b2, out);
}